// round 1
// baseline (speedup 1.0000x reference)
#include <cuda_runtime.h>
#include <cstdint>

// Problem constants (match reference)
#define NXG 100
#define NYG 100
#define NN  (NXG * NYG)          // 10000 nodes
#define ROWVEC (NN / 4)          // 2500 float4 per row

__device__ __forceinline__ float pow125(float x) {
    // x ** 1.25 for x > 0 (inputs are strictly positive by construction)
    return powf(x, 1.25f);
}

__global__ void __launch_bounds__(256)
sgds_fill_kernel(const float* __restrict__ pot,
                 const float* __restrict__ chan,
                 const float* __restrict__ sheet,
                 const float* __restrict__ face_len,
                 const float* __restrict__ link_len,
                 const int*   __restrict__ adj,
                 const int*   __restrict__ lnk,
                 const int*   __restrict__ face_at_link,
                 const int*   __restrict__ head,
                 const int*   __restrict__ tail,
                 const int*   __restrict__ inout,
                 float*       __restrict__ out)
{
    const int i = blockIdx.x;                       // one block per matrix row
    float* row = out + (size_t)i * NN;

    // --- zero the row with vectorized stores (40 KB, 16B-aligned start) ---
    float4* rowv = reinterpret_cast<float4*>(row);
    const float4 z = make_float4(0.f, 0.f, 0.f, 0.f);
    #pragma unroll 4
    for (int v = threadIdx.x; v < ROWVEC; v += blockDim.x) {
        rowv[v] = z;
    }
    __syncthreads();

    // --- lane 0 writes the <=5 nonzeros of this row ---
    if (threadIdx.x == 0) {
        if (inout[i] == 1) {
            // Dirichlet row: identity
            row[i] = 1.0f;
            return;
        }
        const float K_SHEET = 0.01f;
        const float K_CHAN  = 0.1f;
        const float CAVSP   = 2.0f;
        // (1/917 - 1/1000) / 3.34e5, computed in double, used as f32 (matches jnp weak typing)
        const float DISS = (float)((1.0 / 917.0 - 1.0 / 1000.0) / 3.34e5);

        const float cs_i = chan[i];     // NOTE: node-indexed channel_size (reference bug, reproduced)
        const float st_i = sheet[i];

        float diag = 0.0f;
        #pragma unroll
        for (int s = 0; s < 4; s++) {
            const int j = adj[i * 4 + s];
            if (j < 0) continue;
            const int l = lnk[i * 4 + s];

            const float ll = link_len[l];
            const int   h  = head[l];
            const int   t  = tail[l];
            const float g  = (pot[h] - pot[t]) / ll;

            const float rg = rsqrtf(fabsf(g));              // |g|^(-0.5)

            // link fields
            const float chan_q  = -K_CHAN * pow125(chan[l]) * g;
            const float st_link = 0.5f * (sheet[h] + sheet[t]);
            const float sheet_q = -K_SHEET * pow125(st_link) * rg * g;

            // per-slot terms
            const float fl = face_len[face_at_link[l]];
            const float cs = 0.5f * (cs_i + chan[j]);
            const float st = 0.5f * (st_i + sheet[j]);

            const float sheet_flux = -K_SHEET * pow125(st) * rg * fl / ll;
            const float chan_flux  = -K_CHAN  * pow125(cs) * fl / ll;
            const float ch_diss    = fabsf(DISS * chan_q * fl);
            const float sh_diss    = fabsf(DISS * sheet_q * CAVSP * fl);

            const float term = sheet_flux + chan_flux + ch_diss + sh_diss;
            diag += term;
            row[j] = -term;                                  // off-diagonal
        }
        row[i] = diag;                                       // diagonal
    }
}

extern "C" void kernel_launch(void* const* d_in, const int* in_sizes, int n_in,
                              void* d_out, int out_size)
{
    const float* pot          = (const float*)d_in[0];
    const float* channel_size = (const float*)d_in[1];
    const float* sheet        = (const float*)d_in[2];
    const float* face_len     = (const float*)d_in[3];
    const float* link_len     = (const float*)d_in[4];
    const int*   adj          = (const int*)d_in[5];
    const int*   lnk          = (const int*)d_in[6];
    const int*   face_at_link = (const int*)d_in[7];
    const int*   head         = (const int*)d_in[8];
    const int*   tail         = (const int*)d_in[9];
    const int*   inout        = (const int*)d_in[10];

    float* out = (float*)d_out;

    sgds_fill_kernel<<<NN, 256>>>(pot, channel_size, sheet, face_len, link_len,
                                  adj, lnk, face_at_link, head, tail, inout, out);
}

// round 2
// speedup vs baseline: 1.0762x; 1.0762x over previous
#include <cuda_runtime.h>
#include <cstdint>

// Problem constants (match reference)
#define NXG 100
#define NYG 100
#define NN  (NXG * NYG)                   // 10000 nodes
#define TOTAL_ELEMS ((size_t)NN * NN)     // 1e8 floats
#define TOTAL_VEC   (TOTAL_ELEMS / 4)     // 25M float4

#define FILL_BLOCKS  1184                 // 148 SMs * 8
#define FILL_THREADS 256

__device__ __forceinline__ void stcs4(float4* p, float4 v) {
    // streaming (evict-first) 128-bit store
    asm volatile("st.global.cs.v4.f32 [%0], {%1, %2, %3, %4};"
                 :: "l"(p), "f"(v.x), "f"(v.y), "f"(v.z), "f"(v.w) : "memory");
}

__global__ void __launch_bounds__(FILL_THREADS)
sgds_zero_kernel(float4* __restrict__ out)
{
    const float4 z = make_float4(0.f, 0.f, 0.f, 0.f);
    size_t idx = (size_t)blockIdx.x * FILL_THREADS + threadIdx.x;
    const size_t stride = (size_t)FILL_BLOCKS * FILL_THREADS;
    #pragma unroll 4
    for (; idx < TOTAL_VEC; idx += stride) {
        stcs4(out + idx, z);
    }
}

__device__ __forceinline__ float pow125(float x) {
    return powf(x, 1.25f);   // inputs strictly positive
}

__global__ void __launch_bounds__(256)
sgds_patch_kernel(const float* __restrict__ pot,
                  const float* __restrict__ chan,
                  const float* __restrict__ sheet,
                  const float* __restrict__ face_len,
                  const float* __restrict__ link_len,
                  const int*   __restrict__ adj,
                  const int*   __restrict__ lnk,
                  const int*   __restrict__ face_at_link,
                  const int*   __restrict__ head,
                  const int*   __restrict__ tail,
                  const int*   __restrict__ inout,
                  float*       __restrict__ out)
{
    const int i = blockIdx.x * blockDim.x + threadIdx.x;   // one thread per row
    if (i >= NN) return;
    float* row = out + (size_t)i * NN;

    if (inout[i] == 1) {
        row[i] = 1.0f;          // Dirichlet identity row
        return;
    }

    const float K_SHEET = 0.01f;
    const float K_CHAN  = 0.1f;
    const float CAVSP   = 2.0f;
    const float DISS = (float)((1.0 / 917.0 - 1.0 / 1000.0) / 3.34e5);

    const float cs_i = chan[i];   // node-indexed channel_size (reference quirk, reproduced)
    const float st_i = sheet[i];

    const int4 a4 = *reinterpret_cast<const int4*>(adj + (size_t)i * 4);
    const int4 l4 = *reinterpret_cast<const int4*>(lnk + (size_t)i * 4);
    const int ja[4] = {a4.x, a4.y, a4.z, a4.w};
    const int la[4] = {l4.x, l4.y, l4.z, l4.w};

    float diag = 0.0f;
    #pragma unroll
    for (int s = 0; s < 4; s++) {
        const int j = ja[s];
        if (j < 0) continue;
        const int l = la[s];

        const float ll = link_len[l];
        const int   h  = head[l];
        const int   t  = tail[l];
        const float g  = (pot[h] - pot[t]) / ll;

        const float rg = rsqrtf(fabsf(g));                    // |g|^(-0.5)

        const float chan_q  = -K_CHAN * pow125(chan[l]) * g;
        const float st_link = 0.5f * (sheet[h] + sheet[t]);
        const float sheet_q = -K_SHEET * pow125(st_link) * rg * g;

        const float fl = face_len[face_at_link[l]];
        const float cs = 0.5f * (cs_i + chan[j]);
        const float st = 0.5f * (st_i + sheet[j]);

        const float sheet_flux = -K_SHEET * pow125(st) * rg * fl / ll;
        const float chan_flux  = -K_CHAN  * pow125(cs) * fl / ll;
        const float ch_diss    = fabsf(DISS * chan_q * fl);
        const float sh_diss    = fabsf(DISS * sheet_q * CAVSP * fl);

        const float term = sheet_flux + chan_flux + ch_diss + sh_diss;
        diag += term;
        row[j] = -term;
    }
    row[i] = diag;
}

extern "C" void kernel_launch(void* const* d_in, const int* in_sizes, int n_in,
                              void* d_out, int out_size)
{
    const float* pot          = (const float*)d_in[0];
    const float* channel_size = (const float*)d_in[1];
    const float* sheet        = (const float*)d_in[2];
    const float* face_len     = (const float*)d_in[3];
    const float* link_len     = (const float*)d_in[4];
    const int*   adj          = (const int*)d_in[5];
    const int*   lnk          = (const int*)d_in[6];
    const int*   face_at_link = (const int*)d_in[7];
    const int*   head         = (const int*)d_in[8];
    const int*   tail         = (const int*)d_in[9];
    const int*   inout        = (const int*)d_in[10];

    float* out = (float*)d_out;

    sgds_zero_kernel<<<FILL_BLOCKS, FILL_THREADS>>>((float4*)out);
    sgds_patch_kernel<<<(NN + 255) / 256, 256>>>(pot, channel_size, sheet,
                                                 face_len, link_len, adj, lnk,
                                                 face_at_link, head, tail,
                                                 inout, out);
}

// round 3
// speedup vs baseline: 1.1863x; 1.1024x over previous
#include <cuda_runtime.h>
#include <cstdint>

// Problem constants (match reference)
#define NXG 100
#define NYG 100
#define NN  (NXG * NYG)                   // 10000 nodes
#define TOTAL_ELEMS ((size_t)NN * NN)     // 1e8 floats
#define TOTAL_VEC   (TOTAL_ELEMS / 4)     // 25M float4

#define FILL_BLOCKS  1480                 // 148 SMs * 10
#define FILL_THREADS 256

__device__ __forceinline__ void stcs4(float4* p, float4 v) {
    asm volatile("st.global.cs.v4.f32 [%0], {%1, %2, %3, %4};"
                 :: "l"(p), "f"(v.x), "f"(v.y), "f"(v.z), "f"(v.w) : "memory");
}

__global__ void __launch_bounds__(FILL_THREADS)
sgds_zero_kernel(float4* __restrict__ out)
{
    const float4 z = make_float4(0.f, 0.f, 0.f, 0.f);
    size_t idx = (size_t)blockIdx.x * FILL_THREADS + threadIdx.x;
    const size_t stride = (size_t)FILL_BLOCKS * FILL_THREADS;
    #pragma unroll 4
    for (; idx < TOTAL_VEC; idx += stride) {
        stcs4(out + idx, z);
    }
}

__device__ __forceinline__ float pow125(float x) {
    // x^1.25 = x * x^0.25, x > 0 by construction
    return x * sqrtf(sqrtf(x));
}

// One thread per (row, slot): 4 consecutive lanes own one row.
__global__ void __launch_bounds__(256)
sgds_patch_kernel(const float* __restrict__ pot,
                  const float* __restrict__ chan,
                  const float* __restrict__ sheet,
                  const float* __restrict__ face_len,
                  const float* __restrict__ link_len,
                  const int*   __restrict__ adj,
                  const int*   __restrict__ lnk,
                  const int*   __restrict__ face_at_link,
                  const int*   __restrict__ head,
                  const int*   __restrict__ tail,
                  const int*   __restrict__ inout,
                  float*       __restrict__ out)
{
    const int tid = blockIdx.x * blockDim.x + threadIdx.x;
    const int i = tid >> 2;                 // row
    const int s = tid & 3;                  // neighbor slot
    if (i >= NN) return;

    const bool bnd = (inout[i] == 1);       // coalesced-ish broadcast load
    float* row = out + (size_t)i * NN;

    const int j = adj[tid];                 // adj[i*4 + s], coalesced
    const int l = lnk[tid];

    float term = 0.0f;
    int   jw   = -1;

    if (!bnd && j >= 0) {
        const float K_SHEET = 0.01f;
        const float K_CHAN  = 0.1f;
        const float CAVSP   = 2.0f;
        const float DISS = (float)((1.0 / 917.0 - 1.0 / 1000.0) / 3.34e5);

        const float ll = link_len[l];
        const int   h  = head[l];
        const int   t  = tail[l];
        const float g  = (pot[h] - pot[t]) / ll;
        const float rg = rsqrtf(fabsf(g));                  // |g|^(-0.5)

        const float chan_q  = -K_CHAN * pow125(chan[l]) * g;
        const float st_link = 0.5f * (sheet[h] + sheet[t]);
        const float sheet_q = -K_SHEET * pow125(st_link) * rg * g;

        const float fl = face_len[face_at_link[l]];
        const float cs = 0.5f * (chan[i] + chan[j]);        // node-indexed channel_size (ref quirk)
        const float st = 0.5f * (sheet[i] + sheet[j]);

        const float sheet_flux = -K_SHEET * pow125(st) * rg * fl / ll;
        const float chan_flux  = -K_CHAN  * pow125(cs) * fl / ll;
        const float ch_diss    = fabsf(DISS * chan_q * fl);
        const float sh_diss    = fabsf(DISS * sheet_q * CAVSP * fl);

        term = sheet_flux + chan_flux + ch_diss + sh_diss;
        jw   = j;
    }

    // 4-lane diagonal reduction (lanes 4k..4k+3 share a row, same warp)
    float diag = term;
    diag += __shfl_xor_sync(0xFFFFFFFFu, diag, 1, 32);
    diag += __shfl_xor_sync(0xFFFFFFFFu, diag, 2, 32);

    if (jw >= 0) row[jw] = -term;           // off-diagonal
    if (s == 0)  row[i]  = bnd ? 1.0f : diag;   // diagonal / Dirichlet
}

extern "C" void kernel_launch(void* const* d_in, const int* in_sizes, int n_in,
                              void* d_out, int out_size)
{
    const float* pot          = (const float*)d_in[0];
    const float* channel_size = (const float*)d_in[1];
    const float* sheet        = (const float*)d_in[2];
    const float* face_len     = (const float*)d_in[3];
    const float* link_len     = (const float*)d_in[4];
    const int*   adj          = (const int*)d_in[5];
    const int*   lnk          = (const int*)d_in[6];
    const int*   face_at_link = (const int*)d_in[7];
    const int*   head         = (const int*)d_in[8];
    const int*   tail         = (const int*)d_in[9];
    const int*   inout        = (const int*)d_in[10];

    float* out = (float*)d_out;

    sgds_zero_kernel<<<FILL_BLOCKS, FILL_THREADS>>>((float4*)out);
    sgds_patch_kernel<<<(NN * 4 + 255) / 256, 256>>>(pot, channel_size, sheet,
                                                     face_len, link_len, adj, lnk,
                                                     face_at_link, head, tail,
                                                     inout, out);
}

// round 4
// speedup vs baseline: 1.2504x; 1.0540x over previous
#include <cuda_runtime.h>
#include <cstdint>

// Problem constants (match reference)
#define NXG 100
#define NYG 100
#define NN  (NXG * NYG)                   // 10000 nodes
#define ROWVEC (NN / 4)                   // 2500 float4 per row
#define ROWS_PER_BLOCK 8                  // 8 warps/block, 1 warp per row

__device__ __forceinline__ void stcs4(float4* p, float4 v) {
    asm volatile("st.global.cs.v4.f32 [%0], {%1, %2, %3, %4};"
                 :: "l"(p), "f"(v.x), "f"(v.y), "f"(v.z), "f"(v.w) : "memory");
}

__device__ __forceinline__ float pow125(float x) {
    // x^1.25 = x * x^0.25, x > 0 by construction
    return x * sqrtf(sqrtf(x));
}

__global__ void __launch_bounds__(256)
sgds_fused_kernel(const float* __restrict__ pot,
                  const float* __restrict__ chan,
                  const float* __restrict__ sheet,
                  const float* __restrict__ face_len,
                  const float* __restrict__ link_len,
                  const int*   __restrict__ adj,
                  const int*   __restrict__ lnk,
                  const int*   __restrict__ face_at_link,
                  const int*   __restrict__ head,
                  const int*   __restrict__ tail,
                  const int*   __restrict__ inout,
                  float*       __restrict__ out)
{
    const int lane = threadIdx.x & 31;
    const int i    = blockIdx.x * ROWS_PER_BLOCK + (threadIdx.x >> 5);  // row
    float* row = out + (size_t)i * NN;

    // ---- lanes 0-3: compute this row's 4 neighbor-slot terms ----
    const bool bnd = (inout[i] == 1);
    float term = 0.0f;
    int   jw   = -1;

    if (lane < 4 && !bnd) {
        const int j = adj[i * 4 + lane];
        if (j >= 0) {
            const int l = lnk[i * 4 + lane];

            const float K_SHEET = 0.01f;
            const float K_CHAN  = 0.1f;
            const float CAVSP   = 2.0f;
            const float DISS = (float)((1.0 / 917.0 - 1.0 / 1000.0) / 3.34e5);

            const float ll = link_len[l];
            const int   h  = head[l];
            const int   t  = tail[l];
            const float g  = (pot[h] - pot[t]) / ll;
            const float rg = rsqrtf(fabsf(g));              // |g|^(-0.5)

            const float chan_q  = -K_CHAN * pow125(chan[l]) * g;
            const float st_link = 0.5f * (sheet[h] + sheet[t]);
            const float sheet_q = -K_SHEET * pow125(st_link) * rg * g;

            const float fl = face_len[face_at_link[l]];
            const float cs = 0.5f * (chan[i] + chan[j]);    // node-indexed (ref quirk)
            const float st = 0.5f * (sheet[i] + sheet[j]);

            const float sheet_flux = -K_SHEET * pow125(st) * rg * fl / ll;
            const float chan_flux  = -K_CHAN  * pow125(cs) * fl / ll;
            const float ch_diss    = fabsf(DISS * chan_q * fl);
            const float sh_diss    = fabsf(DISS * sheet_q * CAVSP * fl);

            term = sheet_flux + chan_flux + ch_diss + sh_diss;
            jw   = j;
        }
    }

    // diagonal = sum over the 4 slot lanes (lanes 4-31 hold 0 contributions)
    float diag = term;
    diag += __shfl_xor_sync(0xFFFFFFFFu, diag, 1, 32);
    diag += __shfl_xor_sync(0xFFFFFFFFu, diag, 2, 32);
    if (bnd) diag = 1.0f;

    // ---- whole warp streams the row's zeros (2500 float4 = 40 KB) ----
    float4* rowv = reinterpret_cast<float4*>(row);
    const float4 z = make_float4(0.f, 0.f, 0.f, 0.f);
    int v = lane;
    #pragma unroll 1
    for (int it = 0; it < 19; ++it) {        // 19 * 128 = 2432 vectors
        stcs4(rowv + v,      z);
        stcs4(rowv + v + 32, z);
        stcs4(rowv + v + 64, z);
        stcs4(rowv + v + 96, z);
        v += 128;
    }
    for (; v < ROWVEC; v += 32) stcs4(rowv + v, z);   // tail: 68 vectors

    __syncwarp();   // order nonzero patches after the zero stream (exec + mem fence)

    // ---- patch the <=5 nonzeros ----
    if (jw >= 0)  row[jw] = -term;            // off-diagonals (lanes 0-3)
    if (lane == 0) row[i] = diag;             // diagonal / Dirichlet 1.0
}

extern "C" void kernel_launch(void* const* d_in, const int* in_sizes, int n_in,
                              void* d_out, int out_size)
{
    const float* pot          = (const float*)d_in[0];
    const float* channel_size = (const float*)d_in[1];
    const float* sheet        = (const float*)d_in[2];
    const float* face_len     = (const float*)d_in[3];
    const float* link_len     = (const float*)d_in[4];
    const int*   adj          = (const int*)d_in[5];
    const int*   lnk          = (const int*)d_in[6];
    const int*   face_at_link = (const int*)d_in[7];
    const int*   head         = (const int*)d_in[8];
    const int*   tail         = (const int*)d_in[9];
    const int*   inout        = (const int*)d_in[10];

    float* out = (float*)d_out;

    sgds_fused_kernel<<<NN / ROWS_PER_BLOCK, 256>>>(pot, channel_size, sheet,
                                                    face_len, link_len, adj, lnk,
                                                    face_at_link, head, tail,
                                                    inout, out);
}

// round 5
// speedup vs baseline: 1.2739x; 1.0188x over previous
#include <cuda_runtime.h>
#include <cstdint>

#define NXG 100
#define NYG 100
#define NN  (NXG * NYG)                   // 10000 nodes
#define ROWVEC (NN / 4)                   // 2500 float4 per row
#define ROWS_PER_BLOCK 8                  // 8 warps/block, 1 warp per row

__device__ __forceinline__ void stcs4(float4* p, float4 v) {
    asm volatile("st.global.cs.v4.f32 [%0], {%1, %2, %3, %4};"
                 :: "l"(p), "f"(v.x), "f"(v.y), "f"(v.z), "f"(v.w) : "memory");
}

__device__ __forceinline__ float pow125(float x) {
    return x * sqrtf(sqrtf(x));           // x^1.25, x > 0
}

__global__ void __launch_bounds__(256)
sgds_fused_kernel(const float* __restrict__ pot,
                  const float* __restrict__ chan,
                  const float* __restrict__ sheet,
                  const float* __restrict__ face_len,
                  const float* __restrict__ link_len,
                  const int*   __restrict__ adj,
                  const int*   __restrict__ lnk,
                  const int*   __restrict__ face_at_link,
                  const int*   __restrict__ head,
                  const int*   __restrict__ tail,
                  const int*   __restrict__ inout,
                  float*       __restrict__ out)
{
    const int lane = threadIdx.x & 31;
    const int s    = lane & 3;            // slot (redundant across 8 lane-groups)
    const int i    = blockIdx.x * ROWS_PER_BLOCK + (threadIdx.x >> 5);
    float* row = out + (size_t)i * NN;
    float4* rowv = reinterpret_cast<float4*>(row);
    const float4 z = make_float4(0.f, 0.f, 0.f, 0.f);

    // window of vectors that may contain nonzeros: columns [i-100, i+100]
    const int wlo = (i >= 100 ? i - 100 : 0) >> 2;
    const int whi = ((i + 100 < NN) ? i + 100 : NN - 1) >> 2;

    // ---- level-1 loads (issue now, consume after chunk A) ----
    const int j_raw = adj[i * 4 + s];
    const int l_raw = lnk[i * 4 + s];
    const int io    = inout[i];

    int v = lane;
    // ---- chunk A: 16 iterations (512 vectors) ----
    #pragma unroll
    for (int it = 0; it < 16; ++it, v += 32) {
        if (v < wlo || v > whi) stcs4(rowv + v, z);
    }

    // ---- consume L1, issue level-2 ----
    const int  jc   = j_raw >= 0 ? j_raw : 0;
    const int  lc   = l_raw >= 0 ? l_raw : 0;
    const float ll  = link_len[lc];
    const int   h   = head[lc];
    const int   t   = tail[lc];
    const float cl  = chan[lc];
    const int   fal = face_at_link[lc];
    const float cj  = chan[jc];
    const float sj  = sheet[jc];
    const float ci  = chan[i];
    const float si  = sheet[i];

    // ---- chunk B: 16 iterations ----
    #pragma unroll
    for (int it = 0; it < 16; ++it, v += 32) {
        if (v < wlo || v > whi) stcs4(rowv + v, z);
    }

    // ---- consume L2 addresses, issue level-3 ----
    const float ph  = pot[h];
    const float pt  = pot[t];
    const float sh  = sheet[h];
    const float stt = sheet[t];
    const float fl  = face_len[fal];

    // ---- chunk C: remaining vectors ----
    for (; v < ROWVEC; v += 32) {
        if (v < wlo || v > whi) stcs4(rowv + v, z);
    }

    // ---- compute slot term (masked) ----
    const bool bnd   = (io == 1);
    const bool valid = (j_raw >= 0) && !bnd;

    const float K_SHEET = 0.01f;
    const float K_CHAN  = 0.1f;
    const float CAVSP   = 2.0f;
    const float DISS = (float)((1.0 / 917.0 - 1.0 / 1000.0) / 3.34e5);

    const float g  = (ph - pt) / ll;
    const float rg = rsqrtf(fabsf(g));                    // |g|^(-0.5)

    const float chan_q  = -K_CHAN * pow125(cl) * g;
    const float st_link = 0.5f * (sh + stt);
    const float sheet_q = -K_SHEET * pow125(st_link) * rg * g;

    const float cs = 0.5f * (ci + cj);                    // node-indexed (ref quirk)
    const float st = 0.5f * (si + sj);

    const float sheet_flux = -K_SHEET * pow125(st) * rg * fl / ll;
    const float chan_flux  = -K_CHAN  * pow125(cs) * fl / ll;
    const float ch_diss    = fabsf(DISS * chan_q * fl);
    const float sh_diss    = fabsf(DISS * sheet_q * CAVSP * fl);

    float term = valid ? (sheet_flux + chan_flux + ch_diss + sh_diss) : 0.0f;

    // diagonal: sum over the 4 slots (every 4-lane nibble holds slots 0-3)
    float diag = term;
    diag += __shfl_xor_sync(0xFFFFFFFFu, diag, 1, 32);
    diag += __shfl_xor_sync(0xFFFFFFFFu, diag, 2, 32);
    if (bnd) diag = 1.0f;

    // broadcast (col, -term) for slots 0..3 to all lanes
    const int jcol = valid ? j_raw : -1;
    const int   c0 = __shfl_sync(0xFFFFFFFFu, jcol, 0);
    const int   c1 = __shfl_sync(0xFFFFFFFFu, jcol, 1);
    const int   c2 = __shfl_sync(0xFFFFFFFFu, jcol, 2);
    const int   c3 = __shfl_sync(0xFFFFFFFFu, jcol, 3);
    const float v0 = -__shfl_sync(0xFFFFFFFFu, term, 0);
    const float v1 = -__shfl_sync(0xFFFFFFFFu, term, 1);
    const float v2 = -__shfl_sync(0xFFFFFFFFu, term, 2);
    const float v3 = -__shfl_sync(0xFFFFFFFFu, term, 3);

    // ---- merge window: full-width stores with nonzeros selected in ----
    for (int w = wlo + lane; w <= whi; w += 32) {
        const int e = w * 4;
        float4 o;
        #pragma unroll
        for (int k = 0; k < 4; ++k) {
            const int c = e + k;
            float r = (c == i)  ? diag : 0.0f;
            r       = (c == c0) ? v0   : r;
            r       = (c == c1) ? v1   : r;
            r       = (c == c2) ? v2   : r;
            r       = (c == c3) ? v3   : r;
            (&o.x)[k] = r;
        }
        stcs4(rowv + w, o);
    }
}

extern "C" void kernel_launch(void* const* d_in, const int* in_sizes, int n_in,
                              void* d_out, int out_size)
{
    const float* pot          = (const float*)d_in[0];
    const float* channel_size = (const float*)d_in[1];
    const float* sheet        = (const float*)d_in[2];
    const float* face_len     = (const float*)d_in[3];
    const float* link_len     = (const float*)d_in[4];
    const int*   adj          = (const int*)d_in[5];
    const int*   lnk          = (const int*)d_in[6];
    const int*   face_at_link = (const int*)d_in[7];
    const int*   head         = (const int*)d_in[8];
    const int*   tail         = (const int*)d_in[9];
    const int*   inout        = (const int*)d_in[10];

    float* out = (float*)d_out;

    sgds_fused_kernel<<<NN / ROWS_PER_BLOCK, 256>>>(pot, channel_size, sheet,
                                                    face_len, link_len, adj, lnk,
                                                    face_at_link, head, tail,
                                                    inout, out);
}